// round 10
// baseline (speedup 1.0000x reference)
#include <cuda_runtime.h>
#include <math.h>
typedef unsigned long long ull;

#define TSTEPS 512
#define HDIM 1024

#define FFMA2(acc,a,b) asm("fma.rn.f32x2 %0, %1, %2, %0;" : "+l"(acc) : "l"(a), "l"(b))
__device__ __forceinline__ float psum(ull v){
    float x, y;
    asm("mov.b64 {%0,%1}, %2;" : "=f"(x), "=f"(y) : "l"(v));
    return x + y;
}

__device__ int g_cnt[4 * TSTEPS];
__global__ void reset_kernel(){
    int i = blockIdx.x * blockDim.x + threadIdx.x;
    if (i < 4 * TSTEPS) g_cnt[i] = 0;
}

// ---------------------------------------------------------------------------
// Phase 1 (unchanged, proven): C = A @ W + b, 128x128 tile, FFMA2 K-paired.
// ---------------------------------------------------------------------------
#define SA 20
__global__ void __launch_bounds__(256, 1) gemm_xw(
    const float* __restrict__ A, const float* __restrict__ W,
    const float* __restrict__ bias, float* __restrict__ C)
{
    __shared__ float sA[2][128 * SA];
    __shared__ float sB[2][8 * 256];
    const int tid = threadIdx.x;
    const int n0 = blockIdx.x * 128, m0 = blockIdx.y * 128;
    const int ty = tid >> 4, tx = tid & 15;
    const int ar = tid >> 1, ah = (tid & 1) * 8;
    const int wn = tid & 127, wk0 = tid >> 7;

    ull acc[8][8];
    #pragma unroll
    for (int i = 0; i < 8; i++)
        #pragma unroll
        for (int j = 0; j < 8; j++) acc[i][j] = 0ull;

    const float* Ap = A + (size_t)(m0 + ar) * HDIM + ah;
    float4 pa0, pa1; float pw[8];
    pa0 = *(const float4*)Ap;
    pa1 = *(const float4*)(Ap + 4);
    #pragma unroll
    for (int q = 0; q < 4; q++) {
        int kp = wk0 + q * 2;
        pw[q*2+0] = W[(size_t)(2*kp+0) * HDIM + n0 + wn];
        pw[q*2+1] = W[(size_t)(2*kp+1) * HDIM + n0 + wn];
    }
    int buf = 0;
    *(float4*)&sA[0][ar*SA + ah] = pa0;
    *(float4*)&sA[0][ar*SA + ah + 4] = pa1;
    #pragma unroll
    for (int q = 0; q < 4; q++) {
        int kp = wk0 + q * 2;
        sB[0][kp*256 + 2*wn]     = pw[q*2+0];
        sB[0][kp*256 + 2*wn + 1] = pw[q*2+1];
    }
    __syncthreads();

    for (int kt = 0; kt < HDIM / 16; kt++) {
        if (kt < HDIM/16 - 1) {
            const float* An = Ap + (kt + 1) * 16;
            pa0 = *(const float4*)An;
            pa1 = *(const float4*)(An + 4);
            #pragma unroll
            for (int q = 0; q < 4; q++) {
                int kp = wk0 + q * 2;
                int k = (kt + 1) * 16 + 2 * kp;
                pw[q*2+0] = W[(size_t)k * HDIM + n0 + wn];
                pw[q*2+1] = W[(size_t)(k+1) * HDIM + n0 + wn];
            }
        }
        const float* cA = sA[buf];
        const float* cB = sB[buf];
        #pragma unroll
        for (int kq = 0; kq < 4; kq++) {
            ull a0[8], a1[8], w0[8], w1[8];
            #pragma unroll
            for (int i = 0; i < 8; i++) {
                ulonglong2 v = *(const ulonglong2*)&cA[(ty + 16*i) * SA + kq*4];
                a0[i] = v.x; a1[i] = v.y;
            }
            #pragma unroll
            for (int j = 0; j < 8; j++) {
                w0[j] = *(const ull*)&cB[(kq*2+0)*256 + 2*(tx + 16*j)];
                w1[j] = *(const ull*)&cB[(kq*2+1)*256 + 2*(tx + 16*j)];
            }
            #pragma unroll
            for (int i = 0; i < 8; i++)
                #pragma unroll
                for (int j = 0; j < 8; j++) {
                    FFMA2(acc[i][j], a0[i], w0[j]);
                    FFMA2(acc[i][j], a1[i], w1[j]);
                }
        }
        if (kt < HDIM/16 - 1) {
            int nb = buf ^ 1;
            *(float4*)&sA[nb][ar*SA + ah] = pa0;
            *(float4*)&sA[nb][ar*SA + ah + 4] = pa1;
            #pragma unroll
            for (int q = 0; q < 4; q++) {
                int kp = wk0 + q * 2;
                sB[nb][kp*256 + 2*wn]     = pw[q*2+0];
                sB[nb][kp*256 + 2*wn + 1] = pw[q*2+1];
            }
        }
        __syncthreads();
        buf ^= 1;
    }
    #pragma unroll
    for (int j = 0; j < 8; j++) {
        float bb = bias[n0 + tx + 16*j];
        #pragma unroll
        for (int i = 0; i < 8; i++)
            C[(size_t)(m0 + ty + 16*i) * HDIM + n0 + tx + 16*j] = psum(acc[i][j]) + bb;
    }
}

// ---------------------------------------------------------------------------
// Phase 2: persistent scan, 128 CTAs (32 cg x 4 rg), 256 threads, 2x2 tile.
// sW resident [256 kp2][32 n][4 k] (128 KB, loaded once): one LDS.128 = 4
// k-values of one column, FFMA2-pair-ready. h staged row-major, double-
// buffered 128-k chunks: one LDS.128 = 4 k of one row (2-addr broadcast).
// Per 4-k iter/thread: 4 LDS.128 + 8 FFMA2. R1's proven barrier.
// ---------------------------------------------------------------------------
#define SHS2 132
#define SWW (256 * 128)
#define SCAN_SMEM ((SWW + 2 * 32 * SHS2) * 4)

__global__ void __launch_bounds__(256, 1) scan_kernel(
    const float* __restrict__ h0, const float* __restrict__ Wh,
    float* __restrict__ out)
{
    extern __shared__ float sm[];
    float* sW = sm;            // [kp2][n*4 + kk]
    float* sh = sm + SWW;      // [2][32][SHS2]

    const int tid = threadIdx.x;
    const int cg = blockIdx.x, rg = blockIdx.y, c0 = cg * 32;
    const int ty = tid >> 4, tx = tid & 15;   // rows 2ty..+1, cols 2tx..+1

    // one-time: Wh slice in k-quad-transposed layout
    for (int idx = tid; idx < 32 * HDIM; idx += 256) {
        int k = idx >> 5, n = idx & 31;
        sW[(k >> 2) * 128 + n * 4 + (k & 3)] = Wh[(size_t)k * HDIM + c0 + n];
    }
    __syncthreads();

    const int sr = tid >> 3, sk = (tid & 7) * 16;  // staging: row sr, 16 floats
    const int grow = rg * 32 + sr;
    int* cnt = &g_cnt[rg * TSTEPS];

    for (int t = 0; t < TSTEPS; t++) {
        const float* hrow = (t == 0)
            ? h0 + (size_t)grow * HDIM
            : out + ((size_t)grow * TSTEPS + (t - 1)) * HDIM;

        ull a00 = 0, a01 = 0, a10 = 0, a11 = 0;

        float4 pf[4];
        #pragma unroll
        for (int q = 0; q < 4; q++)
            pf[q] = *(const float4*)&hrow[sk + q * 4];

        int buf = 0;
        for (int c = 0; c < 8; c++) {
            float* dst = sh + buf * (32 * SHS2) + sr * SHS2 + sk;
            #pragma unroll
            for (int q = 0; q < 4; q++)
                *(float4*)&dst[q * 4] = pf[q];
            __syncthreads();
            if (c < 7) {
                const float* src = &hrow[(c + 1) * 128 + sk];
                #pragma unroll
                for (int q = 0; q < 4; q++)
                    pf[q] = *(const float4*)&src[q * 4];
            }
            const float* ch = sh + buf * (32 * SHS2);
            const float* r0 = ch + (2 * ty) * SHS2;
            const float* r1 = ch + (2 * ty + 1) * SHS2;
            const float* cw = sW + c * 32 * 128;
            #pragma unroll 8
            for (int kq = 0; kq < 32; kq++) {
                ulonglong2 av0 = *(const ulonglong2*)&r0[kq * 4];
                ulonglong2 av1 = *(const ulonglong2*)&r1[kq * 4];
                ulonglong2 wv0 = *(const ulonglong2*)&cw[kq * 128 + (2 * tx) * 4];
                ulonglong2 wv1 = *(const ulonglong2*)&cw[kq * 128 + (2 * tx + 1) * 4];
                FFMA2(a00, av0.x, wv0.x); FFMA2(a00, av0.y, wv0.y);
                FFMA2(a01, av0.x, wv1.x); FFMA2(a01, av0.y, wv1.y);
                FFMA2(a10, av1.x, wv0.x); FFMA2(a10, av1.y, wv0.y);
                FFMA2(a11, av1.x, wv1.x); FFMA2(a11, av1.y, wv1.y);
            }
            buf ^= 1;
        }

        // epilogue: h = tanh(acc + xw), in place
        {
            int m = rg * 32 + 2 * ty;
            float* p0 = out + ((size_t)m * TSTEPS + t) * HDIM + c0 + 2 * tx;
            float* p1 = p0 + (size_t)TSTEPS * HDIM;
            float2 xw0 = *(const float2*)p0;
            float2 xw1 = *(const float2*)p1;
            float2 o0, o1;
            o0.x = tanhf(psum(a00) + xw0.x);
            o0.y = tanhf(psum(a01) + xw0.y);
            o1.x = tanhf(psum(a10) + xw1.x);
            o1.y = tanhf(psum(a11) + xw1.y);
            *(float2*)p0 = o0;
            *(float2*)p1 = o1;
        }

        if (t < TSTEPS - 1) {
            __threadfence();
            __syncthreads();
            if (tid == 0) {
                atomicAdd(cnt + t, 1);
                while (((volatile int*)cnt)[t] < 32) { }
                __threadfence();
            }
            __syncthreads();
        }
    }
}

extern "C" void kernel_launch(void* const* d_in, const int* in_sizes, int n_in,
                              void* d_out, int out_size) {
    const float* x  = (const float*)d_in[0];
    const float* h0 = (const float*)d_in[1];
    const float* Wx = (const float*)d_in[2];
    const float* Wh = (const float*)d_in[3];
    const float* b  = (const float*)d_in[4];
    float* out = (float*)d_out;

    {
        dim3 grid(HDIM / 128, 65536 / 128);
        gemm_xw<<<grid, 256>>>(x, Wx, b, out);
    }
    reset_kernel<<<4, 512>>>();
    {
        static int done = 0;
        if (!done) {
            cudaFuncSetAttribute(scan_kernel,
                cudaFuncAttributeMaxDynamicSharedMemorySize, SCAN_SMEM);
            done = 1;
        }
        dim3 grid(32, 4);
        scan_kernel<<<grid, 256, SCAN_SMEM>>>(h0, Wh, out);
    }
}

// round 11
// speedup vs baseline: 1.3116x; 1.3116x over previous
#include <cuda_runtime.h>
#include <math.h>
typedef unsigned long long ull;

#define TSTEPS 512
#define HDIM 1024

#define FFMA2(acc,a,b) asm("fma.rn.f32x2 %0, %1, %2, %0;" : "+l"(acc) : "l"(a), "l"(b))
__device__ __forceinline__ float psum(ull v){
    float x, y;
    asm("mov.b64 {%0,%1}, %2;" : "=f"(x), "=f"(y) : "l"(v));
    return x + y;
}

__device__ int g_cnt[4 * TSTEPS];
__global__ void reset_kernel(){
    int i = blockIdx.x * blockDim.x + threadIdx.x;
    if (i < 4 * TSTEPS) g_cnt[i] = 0;
}

// ---------------------------------------------------------------------------
// Phase 1 (unchanged, proven ~2.3ms): C = A @ W + b, 128x128, FFMA2 K-paired.
// ---------------------------------------------------------------------------
#define SA 20
__global__ void __launch_bounds__(256, 1) gemm_xw(
    const float* __restrict__ A, const float* __restrict__ W,
    const float* __restrict__ bias, float* __restrict__ C)
{
    __shared__ float sA[2][128 * SA];
    __shared__ float sB[2][8 * 256];
    const int tid = threadIdx.x;
    const int n0 = blockIdx.x * 128, m0 = blockIdx.y * 128;
    const int ty = tid >> 4, tx = tid & 15;
    const int ar = tid >> 1, ah = (tid & 1) * 8;
    const int wn = tid & 127, wk0 = tid >> 7;

    ull acc[8][8];
    #pragma unroll
    for (int i = 0; i < 8; i++)
        #pragma unroll
        for (int j = 0; j < 8; j++) acc[i][j] = 0ull;

    const float* Ap = A + (size_t)(m0 + ar) * HDIM + ah;
    float4 pa0, pa1; float pw[8];
    pa0 = *(const float4*)Ap;
    pa1 = *(const float4*)(Ap + 4);
    #pragma unroll
    for (int q = 0; q < 4; q++) {
        int kp = wk0 + q * 2;
        pw[q*2+0] = W[(size_t)(2*kp+0) * HDIM + n0 + wn];
        pw[q*2+1] = W[(size_t)(2*kp+1) * HDIM + n0 + wn];
    }
    int buf = 0;
    *(float4*)&sA[0][ar*SA + ah] = pa0;
    *(float4*)&sA[0][ar*SA + ah + 4] = pa1;
    #pragma unroll
    for (int q = 0; q < 4; q++) {
        int kp = wk0 + q * 2;
        sB[0][kp*256 + 2*wn]     = pw[q*2+0];
        sB[0][kp*256 + 2*wn + 1] = pw[q*2+1];
    }
    __syncthreads();

    for (int kt = 0; kt < HDIM / 16; kt++) {
        if (kt < HDIM/16 - 1) {
            const float* An = Ap + (kt + 1) * 16;
            pa0 = *(const float4*)An;
            pa1 = *(const float4*)(An + 4);
            #pragma unroll
            for (int q = 0; q < 4; q++) {
                int kp = wk0 + q * 2;
                int k = (kt + 1) * 16 + 2 * kp;
                pw[q*2+0] = W[(size_t)k * HDIM + n0 + wn];
                pw[q*2+1] = W[(size_t)(k+1) * HDIM + n0 + wn];
            }
        }
        const float* cA = sA[buf];
        const float* cB = sB[buf];
        #pragma unroll
        for (int kq = 0; kq < 4; kq++) {
            ull a0[8], a1[8], w0[8], w1[8];
            #pragma unroll
            for (int i = 0; i < 8; i++) {
                ulonglong2 v = *(const ulonglong2*)&cA[(ty + 16*i) * SA + kq*4];
                a0[i] = v.x; a1[i] = v.y;
            }
            #pragma unroll
            for (int j = 0; j < 8; j++) {
                w0[j] = *(const ull*)&cB[(kq*2+0)*256 + 2*(tx + 16*j)];
                w1[j] = *(const ull*)&cB[(kq*2+1)*256 + 2*(tx + 16*j)];
            }
            #pragma unroll
            for (int i = 0; i < 8; i++)
                #pragma unroll
                for (int j = 0; j < 8; j++) {
                    FFMA2(acc[i][j], a0[i], w0[j]);
                    FFMA2(acc[i][j], a1[i], w1[j]);
                }
        }
        if (kt < HDIM/16 - 1) {
            int nb = buf ^ 1;
            *(float4*)&sA[nb][ar*SA + ah] = pa0;
            *(float4*)&sA[nb][ar*SA + ah + 4] = pa1;
            #pragma unroll
            for (int q = 0; q < 4; q++) {
                int kp = wk0 + q * 2;
                sB[nb][kp*256 + 2*wn]     = pw[q*2+0];
                sB[nb][kp*256 + 2*wn + 1] = pw[q*2+1];
            }
        }
        __syncthreads();
        buf ^= 1;
    }
    #pragma unroll
    for (int j = 0; j < 8; j++) {
        float bb = bias[n0 + tx + 16*j];
        #pragma unroll
        for (int i = 0; i < 8; i++)
            C[(size_t)(m0 + ty + 16*i) * HDIM + n0 + tx + 16*j] = psum(acc[i][j]) + bb;
    }
}

// ---------------------------------------------------------------------------
// Phase 2: persistent scan, 128 CTAs (32 cg x 4 rg), 256 threads.
// 4 k-groups x 64 threads; each group: 32x32 output, 256 k, 4x4 thread tile.
// All loads are 1-wavefront LDS.64. sW k-pair interleaved (128KB, once).
// h staged row-major in 256-k double-buffered chunks. 4-way smem reduction.
// ---------------------------------------------------------------------------
#define SHS 260                       // floats per staged row (16B aligned)
#define SWW (512 * 64)                // sW words
#define SHW (2 * 32 * SHS)            // staging words
#define RSTR 40                       // reduction stride (conflict-free)
#define RDW (4 * 32 * RSTR)           // reduction words
#define SCAN_SMEM ((SWW + SHW + RDW) * 4)

__global__ void __launch_bounds__(256, 1) scan_kernel(
    const float* __restrict__ h0, const float* __restrict__ Wh,
    float* __restrict__ out)
{
    extern __shared__ float sm[];
    float* sW  = sm;                   // [kp][2n+par]
    float* sh  = sm + SWW;             // [2][32][SHS]
    float* red = sm + SWW + SHW;       // [kg][32][RSTR]

    const int tid = threadIdx.x;
    const int cg = blockIdx.x, rg = blockIdx.y, c0 = cg * 32;
    const int kg = tid >> 6;           // k-group 0..3
    const int g  = tid & 63;
    const int c8 = g & 7;              // col position: cols c8+8j
    const int rp = g >> 3;             // row position: rows rp+8i

    // one-time: Wh slice, k-pair interleaved
    for (int idx = tid; idx < 32 * HDIM; idx += 256) {
        int k = idx >> 5, n = idx & 31;
        sW[(k >> 1) * 64 + 2 * n + (k & 1)] = Wh[(size_t)k * HDIM + c0 + n];
    }
    __syncthreads();

    const int sr = tid >> 3, sk = (tid & 7) * 32;   // staging map
    const int grow = rg * 32 + sr;
    const int rr = tid >> 3, cb = (tid & 7) * 4;    // reduce/epilogue map
    int* cnt = &g_cnt[rg * TSTEPS];

    for (int t = 0; t < TSTEPS; t++) {
        const float* hrow = (t == 0)
            ? h0 + (size_t)grow * HDIM
            : out + ((size_t)grow * TSTEPS + (t - 1)) * HDIM;

        ull acc[4][4];
        #pragma unroll
        for (int i = 0; i < 4; i++)
            #pragma unroll
            for (int j = 0; j < 4; j++) acc[i][j] = 0ull;

        float4 pf[8];
        #pragma unroll
        for (int q = 0; q < 8; q++)
            pf[q] = *(const float4*)&hrow[sk + q * 4];

        int buf = 0;
        #pragma unroll 1
        for (int it = 0; it < 4; it++) {
            // store staged chunk
            float* dst = sh + buf * (32 * SHS) + sr * SHS + sk;
            #pragma unroll
            for (int q = 0; q < 8; q++)
                *(float4*)&dst[q * 4] = pf[q];
            __syncthreads();
            // prefetch next chunk
            if (it < 3) {
                const float* src = &hrow[(it + 1) * 256 + sk];
                #pragma unroll
                for (int q = 0; q < 8; q++)
                    pf[q] = *(const float4*)&src[q * 4];
            }
            // compute: group kg's 64-k window of this chunk (32 k-pairs)
            const float* ch = sh + buf * (32 * SHS) + kg * 64;
            const float* wb = sW + (size_t)(it * 128 + kg * 32) * 64;
            #pragma unroll 4
            for (int lkp = 0; lkp < 32; lkp++) {
                ull a[4], w[4];
                #pragma unroll
                for (int i = 0; i < 4; i++)
                    a[i] = *(const ull*)&ch[(rp + 8 * i) * SHS + 2 * lkp];
                #pragma unroll
                for (int j = 0; j < 4; j++)
                    w[j] = *(const ull*)&wb[lkp * 64 + 2 * (c8 + 8 * j)];
                #pragma unroll
                for (int i = 0; i < 4; i++)
                    #pragma unroll
                    for (int j = 0; j < 4; j++)
                        FFMA2(acc[i][j], a[i], w[j]);
            }
            buf ^= 1;
        }

        // write partials (conflict-free: bank = 8*r4 + c8)
        #pragma unroll
        for (int i = 0; i < 4; i++)
            #pragma unroll
            for (int j = 0; j < 4; j++)
                red[kg * (32 * RSTR) + (rp + 8 * i) * RSTR + (c8 + 8 * j)]
                    = psum(acc[i][j]);
        __syncthreads();

        // reduce 4 partials -> tanh epilogue (4 outputs/thread)
        {
            const int m = rg * 32 + rr;
            float* po = out + ((size_t)m * TSTEPS + t) * HDIM + c0 + cb;
            float4 s0 = *(const float4*)&red[0 * (32 * RSTR) + rr * RSTR + cb];
            float4 s1 = *(const float4*)&red[1 * (32 * RSTR) + rr * RSTR + cb];
            float4 s2 = *(const float4*)&red[2 * (32 * RSTR) + rr * RSTR + cb];
            float4 s3 = *(const float4*)&red[3 * (32 * RSTR) + rr * RSTR + cb];
            float4 xw = *(const float4*)po;
            float4 o;
            o.x = tanhf(s0.x + s1.x + s2.x + s3.x + xw.x);
            o.y = tanhf(s0.y + s1.y + s2.y + s3.y + xw.y);
            o.z = tanhf(s0.z + s1.z + s2.z + s3.z + xw.z);
            o.w = tanhf(s0.w + s1.w + s2.w + s3.w + xw.w);
            *(float4*)po = o;
        }

        if (t < TSTEPS - 1) {
            __threadfence();
            __syncthreads();
            if (tid == 0) {
                atomicAdd(cnt + t, 1);
                while (((volatile int*)cnt)[t] < 32) { }
                __threadfence();
            }
            __syncthreads();
        }
    }
}

extern "C" void kernel_launch(void* const* d_in, const int* in_sizes, int n_in,
                              void* d_out, int out_size) {
    const float* x  = (const float*)d_in[0];
    const float* h0 = (const float*)d_in[1];
    const float* Wx = (const float*)d_in[2];
    const float* Wh = (const float*)d_in[3];
    const float* b  = (const float*)d_in[4];
    float* out = (float*)d_out;

    {
        dim3 grid(HDIM / 128, 65536 / 128);
        gemm_xw<<<grid, 256>>>(x, Wx, b, out);
    }
    reset_kernel<<<4, 512>>>();
    {
        static int done = 0;
        if (!done) {
            cudaFuncSetAttribute(scan_kernel,
                cudaFuncAttributeMaxDynamicSharedMemorySize, SCAN_SMEM);
            done = 1;
        }
        dim3 grid(32, 4);
        scan_kernel<<<grid, 256, SCAN_SMEM>>>(h0, Wh, out);
    }
}